// round 16
// baseline (speedup 1.0000x reference)
#include <cuda_runtime.h>
#include <cuda_fp16.h>
#include <math.h>

// Problem constants
#define BATCH 8
#define NCH   384
#define HH    56
#define WW    56
#define HWSZ  3136      // 56*56
#define NKV   784       // 28*28
#define HK    28
#define NG    4
#define GC    96
#define NH    8
#define HC    48

#define YSZ   (BATCH*NCH*HWSZ)     // 9633792
#define PSZ   (BATCH*NG*NKV*2)     // 50176

// Scratch (allocation-free rule: __device__ globals)
static __device__ __half g_qh  [BATCH*NCH*HWSZ];
static __device__ __half g_xh  [BATCH*NCH*HWSZ];
static __device__ __half g_atth[BATCH*NCH*HWSZ];
static __device__ __half g_xsh [BATCH*NCH*NKV];
static __device__ __half g_kh  [BATCH*NCH*NKV];
static __device__ __half g_vh  [BATCH*NCH*NKV];
static __device__ __half g_wh  [4*NCH*NCH];     // Wq, Wk, Wv, Wo fp16
static __device__ float  g_pos [BATCH*NG*NKV*2];

// ---------------------------------------------------------------------------
// mma / ldmatrix / cp.async helpers
// ---------------------------------------------------------------------------
__device__ __forceinline__ void mma16(float* d, const unsigned* a, const unsigned* b) {
    asm("mma.sync.aligned.m16n8k16.row.col.f32.f16.f16.f32 "
        "{%0,%1,%2,%3}, {%4,%5,%6,%7}, {%8,%9}, {%0,%1,%2,%3};"
        : "+f"(d[0]), "+f"(d[1]), "+f"(d[2]), "+f"(d[3])
        : "r"(a[0]), "r"(a[1]), "r"(a[2]), "r"(a[3]), "r"(b[0]), "r"(b[1]));
}
__device__ __forceinline__ void ldsm4(unsigned* r, const __half* p) {
    unsigned addr = (unsigned)__cvta_generic_to_shared(p);
    asm volatile("ldmatrix.sync.aligned.m8n8.x4.shared.b16 {%0,%1,%2,%3}, [%4];"
                 : "=r"(r[0]), "=r"(r[1]), "=r"(r[2]), "=r"(r[3]) : "r"(addr));
}
__device__ __forceinline__ void ldsm4t(unsigned* r, const __half* p) {
    unsigned addr = (unsigned)__cvta_generic_to_shared(p);
    asm volatile("ldmatrix.sync.aligned.m8n8.x4.trans.shared.b16 {%0,%1,%2,%3}, [%4];"
                 : "=r"(r[0]), "=r"(r[1]), "=r"(r[2]), "=r"(r[3]) : "r"(addr));
}
__device__ __forceinline__ void cpa16(const __half* dst, const __half* src, bool pred) {
    unsigned d = (unsigned)__cvta_generic_to_shared(dst);
    int sz = pred ? 16 : 0;
    asm volatile("cp.async.cg.shared.global [%0], [%1], 16, %2;"
                 :: "r"(d), "l"(src), "r"(sz));
}
#define CPA_COMMIT() asm volatile("cp.async.commit_group;")
#define CPA_WAIT1()  asm volatile("cp.async.wait_group 1;")
#define CPA_WAIT0()  asm volatile("cp.async.wait_group 0;")

__device__ __forceinline__ unsigned packh2(float a, float b) {
    half2 h = __floats2half2_rn(a, b);
    return *reinterpret_cast<unsigned*>(&h);
}
__device__ __forceinline__ float ex2(float x) {
    float r; asm("ex2.approx.ftz.f32 %0, %1;" : "=f"(r) : "f"(x)); return r;
}

// ---------------------------------------------------------------------------
// Fused fp32 -> fp16 conversion: x then the 4 weight matrices (one launch).
// ---------------------------------------------------------------------------
#define WN4 (NCH*NCH/4)   // 36864
#define XN4 (YSZ/4)       // 2408448

__global__ __launch_bounds__(256)
void conv_all(const float* __restrict__ x,
              const float* __restrict__ Wq, const float* __restrict__ Wk,
              const float* __restrict__ Wv, const float* __restrict__ Wo,
              __half* __restrict__ xh, __half* __restrict__ wh)
{
    int i = blockIdx.x * 256 + threadIdx.x;
    const float* src;
    half2* dst;
    int r;
    if (i < XN4) {
        src = x; dst = reinterpret_cast<half2*>(xh); r = i;
    } else {
        int r2 = i - XN4;
        int m = r2 / WN4; r = r2 - m * WN4;
        src = (m == 0) ? Wq : (m == 1) ? Wk : (m == 2) ? Wv : Wo;
        dst = reinterpret_cast<half2*>(wh + (size_t)m * NCH * NCH);
    }
    float4 f = reinterpret_cast<const float4*>(src)[r];
    dst[2*r]   = __floats2half2_rn(f.x, f.y);
    dst[2*r+1] = __floats2half2_rn(f.z, f.w);
}

// ---------------------------------------------------------------------------
// fp16 GEMM v2: 3-stage cp.async pipeline, ONE barrier per 32-wide k-step.
// 128x128x32 block tile, 8 warps (2m x 4n).
// ---------------------------------------------------------------------------
#define ASTRH 40
#define BSTRH 136

template<bool OUTH>
__global__ __launch_bounds__(256)
void gemm_h(const __half* __restrict__ A0, const __half* __restrict__ A1,
            const float* __restrict__ bias0, const float* __restrict__ bias1,
            const __half* __restrict__ Bsrc,
            void* __restrict__ C0, void* __restrict__ C1,
            int K, int N)
{
    __shared__ __half As[3][128 * ASTRH];
    __shared__ __half Bs[3][32 * BSTRH];

    bool sel = (A1 != nullptr) && (blockIdx.y >= 3);
    const __half* A    = sel ? A1 : A0;
    const float*  bias = sel ? bias1 : bias0;
    void*         Cv   = sel ? C1 : C0;

    const __half* Bp = Bsrc + (size_t)blockIdx.z * K * N;
    int m0 = (blockIdx.y % 3) * 128, n0 = blockIdx.x * 128;
    int tid = threadIdx.x;
    int wid = tid >> 5, lane = tid & 31;
    int g = lane >> 2, tig = lane & 3;
    int wm = (wid & 1) * 64;
    int wn = (wid >> 1) * 32;
    int l16 = lane & 15, lh = (lane >> 4) * 8;

    int ar = tid >> 1, ac = (tid & 1) * 16;
    int br = tid >> 3, bc = (tid & 7) * 16;

    float acc[4][4][4];
#pragma unroll
    for (int i = 0; i < 4; i++)
#pragma unroll
        for (int j = 0; j < 4; j++)
#pragma unroll
            for (int r = 0; r < 4; r++) acc[i][j][r] = 0.f;

    auto issue = [&](int s, int k0) {
        const __half* asrc = A + (size_t)(m0 + ar) * K + k0 + ac;
        cpa16(&As[s][ar * ASTRH + ac], asrc, true);
        cpa16(&As[s][ar * ASTRH + ac + 8], asrc + 8, true);
        const __half* bsrc = Bp + (size_t)(k0 + br) * N + n0 + bc;
        cpa16(&Bs[s][br * BSTRH + bc], bsrc, n0 + bc < N);
        cpa16(&Bs[s][br * BSTRH + bc + 8], bsrc + 8, n0 + bc + 8 < N);
    };

    // prologue: tiles 0 and 1 in flight
    issue(0, 0);
    CPA_COMMIT();
    issue(1, 32);
    CPA_COMMIT();

    int nIter = K / 32;              // K = 384 -> 12
    for (int i = 0; i < nIter; i++) {
        int s = i % 3;
        CPA_WAIT1();                 // tile i landed (tile i+1 still in flight)
        __syncthreads();             // all warps past previous compute; s-buffer data visible
        // issue tile i+2 into buffer (i+2)%3 (its compute finished >= 1 iter ago)
        if (i + 2 < nIter) issue((i + 2) % 3, (i + 2) * 32);
        CPA_COMMIT();                // keep group counts consistent (may be empty)
#pragma unroll
        for (int kk = 0; kk < 32; kk += 16) {
            unsigned af[4][4], bf[4][2];
#pragma unroll
            for (int mf = 0; mf < 4; mf++)
                ldsm4(af[mf], &As[s][(wm + mf * 16 + l16) * ASTRH + kk + lh]);
#pragma unroll
            for (int nf = 0; nf < 4; nf += 2) {
                unsigned t4[4];
                ldsm4t(t4, &Bs[s][(kk + l16) * BSTRH + wn + nf * 8 + lh]);
                bf[nf][0] = t4[0]; bf[nf][1] = t4[1];
                bf[nf+1][0] = t4[2]; bf[nf+1][1] = t4[3];
            }
#pragma unroll
            for (int mf = 0; mf < 4; mf++)
#pragma unroll
                for (int nf = 0; nf < 4; nf++)
                    mma16(acc[mf][nf], af[mf], bf[nf]);
        }
    }
    __syncthreads();   // protect smem reuse (none) / uniform exit

#pragma unroll
    for (int mf = 0; mf < 4; mf++) {
        int r0 = m0 + wm + mf * 16 + g;
        int r1 = r0 + 8;
        float bv0 = bias[r0], bv1 = bias[r1];
#pragma unroll
        for (int nf = 0; nf < 4; nf++) {
            int cn = n0 + wn + nf * 8 + 2 * tig;
            if (cn < N) {
                if (OUTH) {
                    __half* Ch = (__half*)Cv + (size_t)blockIdx.z * 384 * N;
                    *reinterpret_cast<half2*>(&Ch[(size_t)r0 * N + cn]) =
                        __floats2half2_rn(acc[mf][nf][0] + bv0, acc[mf][nf][1] + bv0);
                    *reinterpret_cast<half2*>(&Ch[(size_t)r1 * N + cn]) =
                        __floats2half2_rn(acc[mf][nf][2] + bv1, acc[mf][nf][3] + bv1);
                } else {
                    float* Cf = (float*)Cv + (size_t)blockIdx.z * 384 * N;
                    *reinterpret_cast<float2*>(&Cf[(size_t)r0 * N + cn]) =
                        make_float2(acc[mf][nf][0] + bv0, acc[mf][nf][1] + bv0);
                    *reinterpret_cast<float2*>(&Cf[(size_t)r1 * N + cn]) =
                        make_float2(acc[mf][nf][2] + bv1, acc[mf][nf][3] + bv1);
                }
            }
        }
    }
}

// ---------------------------------------------------------------------------
// Offset network v5 (R12, unchanged)
// ---------------------------------------------------------------------------
#define HSTR 100

__device__ __forceinline__ float wsum(float v) {
#pragma unroll
    for (int o = 16; o > 0; o >>= 1) v += __shfl_xor_sync(0xffffffffu, v, o);
    return v;
}

__global__ __launch_bounds__(256)
void offset_net(const __half* __restrict__ q,
                const float* __restrict__ dw_w, const float* __restrict__ dw_b,
                const float* __restrict__ ln_g, const float* __restrict__ ln_b,
                const float* __restrict__ pw_w,
                float* __restrict__ pos, float* __restrict__ pos_out,
                float* __restrict__ ref_out)
{
    __shared__ float sh[HK * HSTR];     // [j][c]

    int blk = blockIdx.x;               // bg*28 + i
    int bg = blk / HK;
    int i  = blk - bg * HK;
    int b = bg >> 2, gg = bg & 3;
    int tid = threadIdx.x;

    int ya = (i == 0) ? 0 : (2 * i - 1);
    int yb = 2 * i, yc = 2 * i + 1;
    for (int it = tid; it < GC * HK; it += 256) {
        int c = it / HK, j = it - c * HK;
        const __half* qc = q + ((size_t)(b * NCH + gg * GC + c)) * HWSZ;
        const float* w = dw_w + c * 9;
        float w0 = w[0], w1 = w[1], w2 = w[2];
        float w3 = w[3], w4 = w[4], w5 = w[5];
        float w6 = w[6], w7 = w[7], w8 = w[8];
        if (i == 0) { w0 = 0.f; w1 = 0.f; w2 = 0.f; }
        if (j == 0) { w0 = 0.f; w3 = 0.f; w6 = 0.f; }
        int xa = (j == 0) ? 0 : (2 * j - 1);
        int xb = 2 * j, xc = 2 * j + 1;
        const __half* r0 = qc + ya * WW;
        const __half* r1 = qc + yb * WW;
        const __half* r2 = qc + yc * WW;
        float acc = dw_b[c];
        acc = fmaf(w0, __half2float(r0[xa]), acc);
        acc = fmaf(w1, __half2float(r0[xb]), acc);
        acc = fmaf(w2, __half2float(r0[xc]), acc);
        acc = fmaf(w3, __half2float(r1[xa]), acc);
        acc = fmaf(w4, __half2float(r1[xb]), acc);
        acc = fmaf(w5, __half2float(r1[xc]), acc);
        acc = fmaf(w6, __half2float(r2[xa]), acc);
        acc = fmaf(w7, __half2float(r2[xb]), acc);
        acc = fmaf(w8, __half2float(r2[xc]), acc);
        sh[j * HSTR + c] = acc;
    }
    __syncthreads();

    int warp = tid >> 5, lane = tid & 31;
    for (int j = warp; j < HK; j += 8) {
        const float* hr = &sh[j * HSTR];
        float h0 = hr[lane * 3], h1 = hr[lane * 3 + 1], h2 = hr[lane * 3 + 2];
        float mu = wsum(h0 + h1 + h2) * (1.f / GC);
        float d0 = h0 - mu, d1 = h1 - mu, d2 = h2 - mu;
        float var = wsum(d0 * d0 + d1 * d1 + d2 * d2) * (1.f / GC);
        float inv = rsqrtf(var + 1e-5f);

        float py_p = 0.f, px_p = 0.f;
        float hn[3] = {d0 * inv, d1 * inv, d2 * inv};
#pragma unroll
        for (int e = 0; e < 3; e++) {
            int c = lane * 3 + e;
            float v = hn[e] * ln_g[c] + ln_b[c];
            v = 0.5f * v * (1.f + erff(v * 0.70710678118654752f));
            py_p += pw_w[c] * v;
            px_p += pw_w[GC + c] * v;
        }
        float offy = wsum(py_p);
        float offx = wsum(px_p);

        if (lane == 0) {
            float ry = (0.5f + (float)i) * (1.f / 27.f) * 2.f - 1.f;
            float rx = (0.5f + (float)j) * (1.f / 27.f) * 2.f - 1.f;
            float py = tanhf(offy) * (1.f / 27.f) + ry;
            float px = tanhf(offx) * (1.f / 27.f) + rx;
            size_t o = ((size_t)bg * NKV + i * HK + j) * 2;
            pos[o] = py;     pos[o + 1] = px;
            pos_out[o] = py; pos_out[o + 1] = px;
            ref_out[o] = ry; ref_out[o + 1] = rx;
        }
    }
}

// ---------------------------------------------------------------------------
// Bilinear grid sample from fp16 x -> fp16 xs (unchanged)
// ---------------------------------------------------------------------------
__global__ __launch_bounds__(256)
void grid_sample_k(const __half* __restrict__ x, const float* __restrict__ pos,
                   __half* __restrict__ xs)
{
    int bg = blockIdx.y;
    int b = bg >> 2, g = bg & 3;
    int idx = blockIdx.x * 256 + threadIdx.x;
    int c = idx / NKV, p = idx - c * NKV;

    float py = pos[((size_t)bg * NKV + p) * 2];
    float px = pos[((size_t)bg * NKV + p) * 2 + 1];
    float gx = (px + 1.f) * 0.5f * (WW - 1);
    float gy = (py + 1.f) * 0.5f * (HH - 1);
    float x0f = floorf(gx), y0f = floorf(gy);
    int x0 = (int)x0f, y0 = (int)y0f;
    float wx1 = gx - x0f, wx0 = 1.f - wx1;
    float wy1 = gy - y0f, wy0 = 1.f - wy1;

    const __half* img = x + ((size_t)(b * NCH + g * GC + c)) * HWSZ;

    float v00 = 0.f, v01 = 0.f, v10 = 0.f, v11 = 0.f;
    bool xv0 = (x0 >= 0) && (x0 < WW);
    bool xv1 = (x0 + 1 >= 0) && (x0 + 1 < WW);
    bool yv0 = (y0 >= 0) && (y0 < HH);
    bool yv1 = (y0 + 1 >= 0) && (y0 + 1 < HH);
    if (xv0 && yv0) v00 = __half2float(img[y0 * WW + x0]);
    if (xv1 && yv0) v01 = __half2float(img[y0 * WW + x0 + 1]);
    if (xv0 && yv1) v10 = __half2float(img[(y0 + 1) * WW + x0]);
    if (xv1 && yv1) v11 = __half2float(img[(y0 + 1) * WW + x0 + 1]);

    float acc = v00 * wx0 * wy0 + v01 * wx1 * wy0 + v10 * wx0 * wy1 + v11 * wx1 * wy1;
    xs[((size_t)(b * NCH + g * GC + c)) * NKV + p] = __float2half_rn(acc);
}

// ---------------------------------------------------------------------------
// Flash attention v6 (R15, unchanged): hoisted Q fragments, register P,
// log2 softmax, double-buffered cp.async K/V.
// ---------------------------------------------------------------------------
#define FTM 128
#define FTN 112
#define QSTRH 56     // 48 + 8 pad
#define KSTRH 120    // 112 + 8 pad
#define F_SMEM (30208 * 2)

__global__ __launch_bounds__(256)
void attention_h(const __half* __restrict__ q, const __half* __restrict__ k,
                 const __half* __restrict__ v, __half* __restrict__ out)
{
    extern __shared__ char smraw[];
    __half* qs = (__half*)smraw;                    // [m][c]    128 x QSTRH
    __half* kt = qs + FTM * QSTRH;                  // [2][c][n] 48 x KSTRH
    __half* vt = kt + 2 * HC * KSTRH;

    int head = blockIdx.y;
    int b = head >> 3, hh = head & 7;
    const __half* qp = q + ((size_t)(b * NCH + hh * HC)) * HWSZ;
    const __half* kp = k + ((size_t)(b * NCH + hh * HC)) * NKV;
    const __half* vp = v + ((size_t)(b * NCH + hh * HC)) * NKV;
    __half*       op = out + ((size_t)(b * NCH + hh * HC)) * HWSZ;
    int m0 = blockIdx.x * FTM;
    int tid = threadIdx.x;
    int wid = tid >> 5, lane = tid & 31;
    int g = lane >> 2, tig = lane & 3;
    int l16 = lane & 15, lh = (lane >> 4) * 8;
    int wm = wid * 16;
    const float scale2 = 0.14433756729740643f * 1.4426950408889634f;   // scale*log2(e)

    int row_lo = wm + g, row_hi = wm + g + 8;

    // stage Q (fp16 direct), guarded for tail block
    for (int idx = tid; idx < HC * FTM; idx += 256) {
        int c = idx >> 7, m = idx & 127;
        qs[m * QSTRH + c] = (m0 + m < HWSZ) ? qp[(size_t)c * HWSZ + m0 + m] : __half(0.f);
    }

    auto stage_kv = [&](int s, int n0) {
        __half* kd = kt + s * HC * KSTRH;
        __half* vd = vt + s * HC * KSTRH;
        for (int it = tid; it < 1344; it += 256) {
            int tsel = it / 672;
            int rid = it - tsel * 672;
            int c = rid / 14, gc = (rid - c * 14) * 8;
            const __half* src = (tsel ? vp : kp) + (size_t)c * NKV + n0 + gc;
            cpa16((tsel ? vd : kd) + c * KSTRH + gc, src, true);
        }
    };

    stage_kv(0, 0);
    CPA_COMMIT();

    // hoist loop-invariant Q fragments (needs Q staged -> barrier)
    __syncthreads();
    unsigned aq[3][4];
#pragma unroll
    for (int kk = 0; kk < 3; kk++)
        ldsm4(aq[kk], &qs[(wm + l16) * QSTRH + kk * 16 + lh]);

    float m_lo = -1e30f, m_hi = -1e30f, l_lo = 0.f, l_hi = 0.f;
    float o_acc[6][4];
#pragma unroll
    for (int i = 0; i < 6; i++)
#pragma unroll
        for (int r = 0; r < 4; r++) o_acc[i][r] = 0.f;

    int s = 0;
    for (int t = 0; t < 7; t++) {
        CPA_WAIT0();
        __syncthreads();
        const __half* kts = kt + s * HC * KSTRH;
        const __half* vts = vt + s * HC * KSTRH;

        // ---- S = Q^T K : warp tile 16 x 112 (Q fragments in registers) ----
        float sv[14][4];
#pragma unroll
        for (int j = 0; j < 14; j++)
#pragma unroll
            for (int r = 0; r < 4; r++) sv[j][r] = 0.f;
#pragma unroll
        for (int kk = 0; kk < 3; kk++) {
#pragma unroll
            for (int j16 = 0; j16 < 7; j16++) {
                unsigned t4[4];
                ldsm4t(t4, &kts[(kk * 16 + l16) * KSTRH + j16 * 16 + lh]);
                mma16(sv[2 * j16],     aq[kk], t4);
                mma16(sv[2 * j16 + 1], aq[kk], t4 + 2);
            }
        }

        // prefetch next K/V tile
        if (t < 6) stage_kv(s ^ 1, (t + 1) * FTN);
        CPA_COMMIT();

        // ---- row max ----
        float mx_lo = -1e30f, mx_hi = -1e30f;
#pragma unroll
        for (int j = 0; j < 14; j++) {
            mx_lo = fmaxf(mx_lo, fmaxf(sv[j][0], sv[j][1]));
            mx_hi = fmaxf(mx_hi, fmaxf(sv[j][2], sv[j][3]));
        }
#pragma unroll
        for (int o = 1; o < 4; o <<= 1) {
            mx_lo = fmaxf(mx_lo, __shfl_xor_sync(0xffffffffu, mx_lo, o));
            mx_hi = fmaxf(mx_hi, __shfl_xor_sync(0xffffffffu, mx_hi, o));
        }
        float mn_lo = fmaxf(m_lo, mx_lo * scale2);   // log2 units
        float mn_hi = fmaxf(m_hi, mx_hi * scale2);
        float al_lo = ex2(m_lo - mn_lo);
        float al_hi = ex2(m_hi - mn_hi);
        m_lo = mn_lo; m_hi = mn_hi;

        // ---- p = 2^(scale2*s - m) -> packed A fragments ----
        unsigned pk[7][4];
        float sm_lo = 0.f, sm_hi = 0.f;
#pragma unroll
        for (int j16 = 0; j16 < 7; j16++) {
#pragma unroll
            for (int h = 0; h < 2; h++) {
                float* svp = sv[2 * j16 + h];
                float p0 = ex2(fmaf(svp[0], scale2, -mn_lo));
                float p1 = ex2(fmaf(svp[1], scale2, -mn_lo));
                float p2 = ex2(fmaf(svp[2], scale2, -mn_hi));
                float p3 = ex2(fmaf(svp[3], scale2, -mn_hi));
                sm_lo += p0 + p1; sm_hi += p2 + p3;
                pk[j16][2 * h]     = packh2(p0, p1);
                pk[j16][2 * h + 1] = packh2(p2, p3);
            }
        }
#pragma unroll
        for (int o = 1; o < 4; o <<= 1) {
            sm_lo += __shfl_xor_sync(0xffffffffu, sm_lo, o);
            sm_hi += __shfl_xor_sync(0xffffffffu, sm_hi, o);
        }
        l_lo = l_lo * al_lo + sm_lo;
        l_hi = l_hi * al_hi + sm_hi;
#pragma unroll
        for (int i = 0; i < 6; i++) {
            o_acc[i][0] *= al_lo; o_acc[i][1] *= al_lo;
            o_acc[i][2] *= al_hi; o_acc[i][3] *= al_hi;
        }

        // ---- PV: registers P x smem V, 16m x 48c ----
#pragma unroll
        for (int j16 = 0; j16 < 7; j16++) {
#pragma unroll
            for (int ci = 0; ci < 6; ci++) {
                unsigned bf[2];
                bf[0] = *reinterpret_cast<const unsigned*>(&vts[(ci * 8 + g) * KSTRH + j16 * 16 + 2 * tig]);
                bf[1] = *reinterpret_cast<const unsigned*>(&vts[(ci * 8 + g) * KSTRH + j16 * 16 + 8 + 2 * tig]);
                mma16(o_acc[ci], pk[j16], bf);
            }
        }
        s ^= 1;
    }

    // ---- epilogue ----
    float il_lo = 1.f / l_lo;
    float il_hi = 1.f / l_hi;
    bool ok_lo = (m0 + row_lo) < HWSZ;
    bool ok_hi = (m0 + row_hi) < HWSZ;
#pragma unroll
    for (int ci = 0; ci < 6; ci++) {
        int cc = ci * 8 + 2 * tig;
        if (ok_lo) {
            op[(size_t)cc * HWSZ + m0 + row_lo]       = __float2half_rn(o_acc[ci][0] * il_lo);
            op[(size_t)(cc + 1) * HWSZ + m0 + row_lo] = __float2half_rn(o_acc[ci][1] * il_lo);
        }
        if (ok_hi) {
            op[(size_t)cc * HWSZ + m0 + row_hi]       = __float2half_rn(o_acc[ci][2] * il_hi);
            op[(size_t)(cc + 1) * HWSZ + m0 + row_hi] = __float2half_rn(o_acc[ci][3] * il_hi);
        }
    }
}

// ---------------------------------------------------------------------------
extern "C" void kernel_launch(void* const* d_in, const int* in_sizes, int n_in,
                              void* d_out, int out_size)
{
    const float* x   = (const float*)d_in[0];
    const float* Wq  = (const float*)d_in[1];
    const float* bq  = (const float*)d_in[2];
    const float* Wk  = (const float*)d_in[3];
    const float* bk  = (const float*)d_in[4];
    const float* Wv  = (const float*)d_in[5];
    const float* bv  = (const float*)d_in[6];
    const float* Wo  = (const float*)d_in[7];
    const float* bo  = (const float*)d_in[8];
    const float* dww = (const float*)d_in[9];
    const float* dwb = (const float*)d_in[10];
    const float* lng = (const float*)d_in[11];
    const float* lnb = (const float*)d_in[12];
    const float* pww = (const float*)d_in[13];
    float* out = (float*)d_out;

    float *pos;
    __half *qh, *xh, *atth, *xsh, *kh, *vh, *wh;
    cudaGetSymbolAddress((void**)&pos,  g_pos);
    cudaGetSymbolAddress((void**)&qh,   g_qh);
    cudaGetSymbolAddress((void**)&xh,   g_xh);
    cudaGetSymbolAddress((void**)&atth, g_atth);
    cudaGetSymbolAddress((void**)&xsh,  g_xsh);
    cudaGetSymbolAddress((void**)&kh,   g_kh);
    cudaGetSymbolAddress((void**)&vh,   g_vh);
    cudaGetSymbolAddress((void**)&wh,   g_wh);

    __half* whq = wh;
    __half* whk = wh + NCH * NCH;
    __half* whv = wh + 2 * NCH * NCH;
    __half* who = wh + 3 * NCH * NCH;

    cudaFuncSetAttribute(attention_h, cudaFuncAttributeMaxDynamicSharedMemorySize, F_SMEM);

    // 0) all fp32->fp16 conversions in one launch
    conv_all<<<(XN4 + 4 * WN4) / 256, 256>>>(x, Wq, Wk, Wv, Wo, xh, wh);

    dim3 gbig((HWSZ + 127) / 128, 3, BATCH);   // 25 x 3 x 8
    dim3 gkv((NKV + 127) / 128, 6, BATCH);     // 7 x 6 x 8 (k + v fused)

    // 1) q = Wq x + bq  (fp16 out)
    gemm_h<true><<<gbig, 256>>>(whq, nullptr, bq, nullptr, xh, qh, nullptr, NCH, HWSZ);
    // 2) offset net -> pos
    offset_net<<<BATCH * NG * HK, 256>>>(qh, dww, dwb, lng, lnb, pww,
                                         pos, out + YSZ, out + YSZ + PSZ);
    // 3) grid sample (fp16 in/out)
    grid_sample_k<<<dim3((GC * NKV) / 256, BATCH * NG), 256>>>(xh, pos, xsh);
    // 4) k and v in one launch (fp16 out)
    gemm_h<true><<<gkv, 256>>>(whk, whv, bk, bv, xsh, kh, vh, NCH, NKV);
    // 5) flash attention -> atth (fp16)
    attention_h<<<dim3((HWSZ + FTM - 1) / FTM, BATCH * NH), 256, F_SMEM>>>(qh, kh, vh, atth);
    // 6) y = Wo att + bo
    gemm_h<false><<<gbig, 256>>>(who, nullptr, bo, nullptr, atth, out, nullptr, NCH, HWSZ);
}

// round 17
// speedup vs baseline: 1.5583x; 1.5583x over previous
#include <cuda_runtime.h>
#include <cuda_fp16.h>
#include <math.h>

// Problem constants
#define BATCH 8
#define NCH   384
#define HH    56
#define WW    56
#define HWSZ  3136      // 56*56
#define NKV   784       // 28*28
#define HK    28
#define NG    4
#define GC    96
#define NH    8
#define HC    48

#define YSZ   (BATCH*NCH*HWSZ)     // 9633792
#define PSZ   (BATCH*NG*NKV*2)     // 50176

// Scratch (allocation-free rule: __device__ globals)
static __device__ __half g_qh  [BATCH*NCH*HWSZ];
static __device__ __half g_xh  [BATCH*NCH*HWSZ];
static __device__ __half g_atth[BATCH*NCH*HWSZ];
static __device__ __half g_xsh [BATCH*NCH*NKV];
static __device__ __half g_kh  [BATCH*NCH*NKV];
static __device__ __half g_vh  [BATCH*NCH*NKV];
static __device__ __half g_wh  [4*NCH*NCH];     // Wq, Wk, Wv, Wo fp16
static __device__ float  g_pos [BATCH*NG*NKV*2];

// ---------------------------------------------------------------------------
// mma / ldmatrix / cp.async helpers
// ---------------------------------------------------------------------------
__device__ __forceinline__ void mma16(float* d, const unsigned* a, const unsigned* b) {
    asm("mma.sync.aligned.m16n8k16.row.col.f32.f16.f16.f32 "
        "{%0,%1,%2,%3}, {%4,%5,%6,%7}, {%8,%9}, {%0,%1,%2,%3};"
        : "+f"(d[0]), "+f"(d[1]), "+f"(d[2]), "+f"(d[3])
        : "r"(a[0]), "r"(a[1]), "r"(a[2]), "r"(a[3]), "r"(b[0]), "r"(b[1]));
}
__device__ __forceinline__ void ldsm4(unsigned* r, const __half* p) {
    unsigned addr = (unsigned)__cvta_generic_to_shared(p);
    asm volatile("ldmatrix.sync.aligned.m8n8.x4.shared.b16 {%0,%1,%2,%3}, [%4];"
                 : "=r"(r[0]), "=r"(r[1]), "=r"(r[2]), "=r"(r[3]) : "r"(addr));
}
__device__ __forceinline__ void ldsm4t(unsigned* r, const __half* p) {
    unsigned addr = (unsigned)__cvta_generic_to_shared(p);
    asm volatile("ldmatrix.sync.aligned.m8n8.x4.trans.shared.b16 {%0,%1,%2,%3}, [%4];"
                 : "=r"(r[0]), "=r"(r[1]), "=r"(r[2]), "=r"(r[3]) : "r"(addr));
}
__device__ __forceinline__ void cpa16(const __half* dst, const __half* src, bool pred) {
    unsigned d = (unsigned)__cvta_generic_to_shared(dst);
    int sz = pred ? 16 : 0;
    asm volatile("cp.async.cg.shared.global [%0], [%1], 16, %2;"
                 :: "r"(d), "l"(src), "r"(sz));
}
#define CPA_COMMIT() asm volatile("cp.async.commit_group;")
#define CPA_WAIT1()  asm volatile("cp.async.wait_group 1;")
#define CPA_WAIT0()  asm volatile("cp.async.wait_group 0;")

__device__ __forceinline__ unsigned packh2(float a, float b) {
    half2 h = __floats2half2_rn(a, b);
    return *reinterpret_cast<unsigned*>(&h);
}
__device__ __forceinline__ float ex2(float x) {
    float r; asm("ex2.approx.ftz.f32 %0, %1;" : "=f"(r) : "f"(x)); return r;
}

// ---------------------------------------------------------------------------
// Fused fp32 -> fp16 conversion: x then the 4 weight matrices (one launch).
// ---------------------------------------------------------------------------
#define WN4 (NCH*NCH/4)   // 36864
#define XN4 (YSZ/4)       // 2408448

__global__ __launch_bounds__(256)
void conv_all(const float* __restrict__ x,
              const float* __restrict__ Wq, const float* __restrict__ Wk,
              const float* __restrict__ Wv, const float* __restrict__ Wo,
              __half* __restrict__ xh, __half* __restrict__ wh)
{
    int i = blockIdx.x * 256 + threadIdx.x;
    const float* src;
    half2* dst;
    int r;
    if (i < XN4) {
        src = x; dst = reinterpret_cast<half2*>(xh); r = i;
    } else {
        int r2 = i - XN4;
        int m = r2 / WN4; r = r2 - m * WN4;
        src = (m == 0) ? Wq : (m == 1) ? Wk : (m == 2) ? Wv : Wo;
        dst = reinterpret_cast<half2*>(wh + (size_t)m * NCH * NCH);
    }
    float4 f = reinterpret_cast<const float4*>(src)[r];
    dst[2*r]   = __floats2half2_rn(f.x, f.y);
    dst[2*r+1] = __floats2half2_rn(f.z, f.w);
}

// ---------------------------------------------------------------------------
// fp16 GEMM (R15 two-stage version, reverted from R16)
// ---------------------------------------------------------------------------
#define ASTRH 40
#define BSTRH 136

template<bool OUTH>
__global__ __launch_bounds__(256)
void gemm_h(const __half* __restrict__ A0, const __half* __restrict__ A1,
            const float* __restrict__ bias0, const float* __restrict__ bias1,
            const __half* __restrict__ Bsrc,
            void* __restrict__ C0, void* __restrict__ C1,
            int K, int N)
{
    __shared__ __half As[2][128 * ASTRH];
    __shared__ __half Bs[2][32 * BSTRH];

    bool sel = (A1 != nullptr) && (blockIdx.y >= 3);
    const __half* A    = sel ? A1 : A0;
    const float*  bias = sel ? bias1 : bias0;
    void*         Cv   = sel ? C1 : C0;

    const __half* Bp = Bsrc + (size_t)blockIdx.z * K * N;
    int m0 = (blockIdx.y % 3) * 128, n0 = blockIdx.x * 128;
    int tid = threadIdx.x;
    int wid = tid >> 5, lane = tid & 31;
    int g = lane >> 2, tig = lane & 3;
    int wm = (wid & 1) * 64;
    int wn = (wid >> 1) * 32;
    int l16 = lane & 15, lh = (lane >> 4) * 8;

    int ar = tid >> 1, ac = (tid & 1) * 16;
    int br = tid >> 3, bc = (tid & 7) * 16;

    float acc[4][4][4];
#pragma unroll
    for (int i = 0; i < 4; i++)
#pragma unroll
        for (int j = 0; j < 4; j++)
#pragma unroll
            for (int r = 0; r < 4; r++) acc[i][j][r] = 0.f;

    auto issue = [&](int s, int k0) {
        const __half* asrc = A + (size_t)(m0 + ar) * K + k0 + ac;
        cpa16(&As[s][ar * ASTRH + ac], asrc, true);
        cpa16(&As[s][ar * ASTRH + ac + 8], asrc + 8, true);
        const __half* bsrc = Bp + (size_t)(k0 + br) * N + n0 + bc;
        cpa16(&Bs[s][br * BSTRH + bc], bsrc, n0 + bc < N);
        cpa16(&Bs[s][br * BSTRH + bc + 8], bsrc + 8, n0 + bc + 8 < N);
    };

    issue(0, 0);
    CPA_COMMIT();

    int s = 0;
    for (int k0 = 0; k0 < K; k0 += 32, s ^= 1) {
        if (k0 + 32 < K) issue(s ^ 1, k0 + 32);
        CPA_COMMIT();
        CPA_WAIT1();
        __syncthreads();
#pragma unroll
        for (int kk = 0; kk < 32; kk += 16) {
            unsigned af[4][4], bf[4][2];
#pragma unroll
            for (int mf = 0; mf < 4; mf++)
                ldsm4(af[mf], &As[s][(wm + mf * 16 + l16) * ASTRH + kk + lh]);
#pragma unroll
            for (int nf = 0; nf < 4; nf += 2) {
                unsigned t4[4];
                ldsm4t(t4, &Bs[s][(kk + l16) * BSTRH + wn + nf * 8 + lh]);
                bf[nf][0] = t4[0]; bf[nf][1] = t4[1];
                bf[nf+1][0] = t4[2]; bf[nf+1][1] = t4[3];
            }
#pragma unroll
            for (int mf = 0; mf < 4; mf++)
#pragma unroll
                for (int nf = 0; nf < 4; nf++)
                    mma16(acc[mf][nf], af[mf], bf[nf]);
        }
        __syncthreads();
    }

#pragma unroll
    for (int mf = 0; mf < 4; mf++) {
        int r0 = m0 + wm + mf * 16 + g;
        int r1 = r0 + 8;
        float bv0 = bias[r0], bv1 = bias[r1];
#pragma unroll
        for (int nf = 0; nf < 4; nf++) {
            int cn = n0 + wn + nf * 8 + 2 * tig;
            if (cn < N) {
                if (OUTH) {
                    __half* Ch = (__half*)Cv + (size_t)blockIdx.z * 384 * N;
                    *reinterpret_cast<half2*>(&Ch[(size_t)r0 * N + cn]) =
                        __floats2half2_rn(acc[mf][nf][0] + bv0, acc[mf][nf][1] + bv0);
                    *reinterpret_cast<half2*>(&Ch[(size_t)r1 * N + cn]) =
                        __floats2half2_rn(acc[mf][nf][2] + bv1, acc[mf][nf][3] + bv1);
                } else {
                    float* Cf = (float*)Cv + (size_t)blockIdx.z * 384 * N;
                    *reinterpret_cast<float2*>(&Cf[(size_t)r0 * N + cn]) =
                        make_float2(acc[mf][nf][0] + bv0, acc[mf][nf][1] + bv0);
                    *reinterpret_cast<float2*>(&Cf[(size_t)r1 * N + cn]) =
                        make_float2(acc[mf][nf][2] + bv1, acc[mf][nf][3] + bv1);
                }
            }
        }
    }
}

// ---------------------------------------------------------------------------
// Offset network v5 (R12/R15, unchanged)
// ---------------------------------------------------------------------------
#define HSTR 100

__device__ __forceinline__ float wsum(float v) {
#pragma unroll
    for (int o = 16; o > 0; o >>= 1) v += __shfl_xor_sync(0xffffffffu, v, o);
    return v;
}

__global__ __launch_bounds__(256)
void offset_net(const __half* __restrict__ q,
                const float* __restrict__ dw_w, const float* __restrict__ dw_b,
                const float* __restrict__ ln_g, const float* __restrict__ ln_b,
                const float* __restrict__ pw_w,
                float* __restrict__ pos, float* __restrict__ pos_out,
                float* __restrict__ ref_out)
{
    __shared__ float sh[HK * HSTR];     // [j][c]

    int blk = blockIdx.x;               // bg*28 + i
    int bg = blk / HK;
    int i  = blk - bg * HK;
    int b = bg >> 2, gg = bg & 3;
    int tid = threadIdx.x;

    int ya = (i == 0) ? 0 : (2 * i - 1);
    int yb = 2 * i, yc = 2 * i + 1;
    for (int it = tid; it < GC * HK; it += 256) {
        int c = it / HK, j = it - c * HK;
        const __half* qc = q + ((size_t)(b * NCH + gg * GC + c)) * HWSZ;
        const float* w = dw_w + c * 9;
        float w0 = w[0], w1 = w[1], w2 = w[2];
        float w3 = w[3], w4 = w[4], w5 = w[5];
        float w6 = w[6], w7 = w[7], w8 = w[8];
        if (i == 0) { w0 = 0.f; w1 = 0.f; w2 = 0.f; }
        if (j == 0) { w0 = 0.f; w3 = 0.f; w6 = 0.f; }
        int xa = (j == 0) ? 0 : (2 * j - 1);
        int xb = 2 * j, xc = 2 * j + 1;
        const __half* r0 = qc + ya * WW;
        const __half* r1 = qc + yb * WW;
        const __half* r2 = qc + yc * WW;
        float acc = dw_b[c];
        acc = fmaf(w0, __half2float(r0[xa]), acc);
        acc = fmaf(w1, __half2float(r0[xb]), acc);
        acc = fmaf(w2, __half2float(r0[xc]), acc);
        acc = fmaf(w3, __half2float(r1[xa]), acc);
        acc = fmaf(w4, __half2float(r1[xb]), acc);
        acc = fmaf(w5, __half2float(r1[xc]), acc);
        acc = fmaf(w6, __half2float(r2[xa]), acc);
        acc = fmaf(w7, __half2float(r2[xb]), acc);
        acc = fmaf(w8, __half2float(r2[xc]), acc);
        sh[j * HSTR + c] = acc;
    }
    __syncthreads();

    int warp = tid >> 5, lane = tid & 31;
    for (int j = warp; j < HK; j += 8) {
        const float* hr = &sh[j * HSTR];
        float h0 = hr[lane * 3], h1 = hr[lane * 3 + 1], h2 = hr[lane * 3 + 2];
        float mu = wsum(h0 + h1 + h2) * (1.f / GC);
        float d0 = h0 - mu, d1 = h1 - mu, d2 = h2 - mu;
        float var = wsum(d0 * d0 + d1 * d1 + d2 * d2) * (1.f / GC);
        float inv = rsqrtf(var + 1e-5f);

        float py_p = 0.f, px_p = 0.f;
        float hn[3] = {d0 * inv, d1 * inv, d2 * inv};
#pragma unroll
        for (int e = 0; e < 3; e++) {
            int c = lane * 3 + e;
            float v = hn[e] * ln_g[c] + ln_b[c];
            v = 0.5f * v * (1.f + erff(v * 0.70710678118654752f));
            py_p += pw_w[c] * v;
            px_p += pw_w[GC + c] * v;
        }
        float offy = wsum(py_p);
        float offx = wsum(px_p);

        if (lane == 0) {
            float ry = (0.5f + (float)i) * (1.f / 27.f) * 2.f - 1.f;
            float rx = (0.5f + (float)j) * (1.f / 27.f) * 2.f - 1.f;
            float py = tanhf(offy) * (1.f / 27.f) + ry;
            float px = tanhf(offx) * (1.f / 27.f) + rx;
            size_t o = ((size_t)bg * NKV + i * HK + j) * 2;
            pos[o] = py;     pos[o + 1] = px;
            pos_out[o] = py; pos_out[o + 1] = px;
            ref_out[o] = ry; ref_out[o + 1] = rx;
        }
    }
}

// ---------------------------------------------------------------------------
// Bilinear grid sample v2: two adjacent positions per thread (float4 pos
// load, half2 store). fp16 in/out.
// ---------------------------------------------------------------------------
#define NKV2 (NKV/2)   // 392

__global__ __launch_bounds__(256)
void grid_sample_k(const __half* __restrict__ x, const float* __restrict__ pos,
                   __half* __restrict__ xs)
{
    int bg = blockIdx.y;
    int b = bg >> 2, g = bg & 3;
    int idx = blockIdx.x * 256 + threadIdx.x;   // < GC*NKV2 = 37632
    int c = idx / NKV2, p2 = (idx - c * NKV2) * 2;

    float4 pp = *reinterpret_cast<const float4*>(&pos[((size_t)bg * NKV + p2) * 2]);
    const __half* img = x + ((size_t)(b * NCH + g * GC + c)) * HWSZ;

    float res[2];
#pragma unroll
    for (int e = 0; e < 2; e++) {
        float py = (e == 0) ? pp.x : pp.z;
        float px = (e == 0) ? pp.y : pp.w;
        float gx = (px + 1.f) * 0.5f * (WW - 1);
        float gy = (py + 1.f) * 0.5f * (HH - 1);
        float x0f = floorf(gx), y0f = floorf(gy);
        int x0 = (int)x0f, y0 = (int)y0f;
        float wx1 = gx - x0f, wx0 = 1.f - wx1;
        float wy1 = gy - y0f, wy0 = 1.f - wy1;

        float v00 = 0.f, v01 = 0.f, v10 = 0.f, v11 = 0.f;
        bool xv0 = (x0 >= 0) && (x0 < WW);
        bool xv1 = (x0 + 1 >= 0) && (x0 + 1 < WW);
        bool yv0 = (y0 >= 0) && (y0 < HH);
        bool yv1 = (y0 + 1 >= 0) && (y0 + 1 < HH);
        if (xv0 && yv0) v00 = __half2float(img[y0 * WW + x0]);
        if (xv1 && yv0) v01 = __half2float(img[y0 * WW + x0 + 1]);
        if (xv0 && yv1) v10 = __half2float(img[(y0 + 1) * WW + x0]);
        if (xv1 && yv1) v11 = __half2float(img[(y0 + 1) * WW + x0 + 1]);

        res[e] = v00 * wx0 * wy0 + v01 * wx1 * wy0 + v10 * wx0 * wy1 + v11 * wx1 * wy1;
    }
    *reinterpret_cast<half2*>(&xs[((size_t)(b * NCH + g * GC + c)) * NKV + p2]) =
        __floats2half2_rn(res[0], res[1]);
}

// ---------------------------------------------------------------------------
// Flash attention v6 (R15, unchanged): hoisted Q fragments, register P,
// log2 softmax, double-buffered cp.async K/V.
// ---------------------------------------------------------------------------
#define FTM 128
#define FTN 112
#define QSTRH 56     // 48 + 8 pad
#define KSTRH 120    // 112 + 8 pad
#define F_SMEM (30208 * 2)

__global__ __launch_bounds__(256)
void attention_h(const __half* __restrict__ q, const __half* __restrict__ k,
                 const __half* __restrict__ v, __half* __restrict__ out)
{
    extern __shared__ char smraw[];
    __half* qs = (__half*)smraw;                    // [m][c]    128 x QSTRH
    __half* kt = qs + FTM * QSTRH;                  // [2][c][n] 48 x KSTRH
    __half* vt = kt + 2 * HC * KSTRH;

    int head = blockIdx.y;
    int b = head >> 3, hh = head & 7;
    const __half* qp = q + ((size_t)(b * NCH + hh * HC)) * HWSZ;
    const __half* kp = k + ((size_t)(b * NCH + hh * HC)) * NKV;
    const __half* vp = v + ((size_t)(b * NCH + hh * HC)) * NKV;
    __half*       op = out + ((size_t)(b * NCH + hh * HC)) * HWSZ;
    int m0 = blockIdx.x * FTM;
    int tid = threadIdx.x;
    int wid = tid >> 5, lane = tid & 31;
    int g = lane >> 2, tig = lane & 3;
    int l16 = lane & 15, lh = (lane >> 4) * 8;
    int wm = wid * 16;
    const float scale2 = 0.14433756729740643f * 1.4426950408889634f;   // scale*log2(e)

    int row_lo = wm + g, row_hi = wm + g + 8;

    // stage Q (fp16 direct), guarded for tail block
    for (int idx = tid; idx < HC * FTM; idx += 256) {
        int c = idx >> 7, m = idx & 127;
        qs[m * QSTRH + c] = (m0 + m < HWSZ) ? qp[(size_t)c * HWSZ + m0 + m] : __half(0.f);
    }

    auto stage_kv = [&](int s, int n0) {
        __half* kd = kt + s * HC * KSTRH;
        __half* vd = vt + s * HC * KSTRH;
        for (int it = tid; it < 1344; it += 256) {
            int tsel = it / 672;
            int rid = it - tsel * 672;
            int c = rid / 14, gc = (rid - c * 14) * 8;
            const __half* src = (tsel ? vp : kp) + (size_t)c * NKV + n0 + gc;
            cpa16((tsel ? vd : kd) + c * KSTRH + gc, src, true);
        }
    };

    stage_kv(0, 0);
    CPA_COMMIT();

    // hoist loop-invariant Q fragments (needs Q staged -> barrier)
    __syncthreads();
    unsigned aq[3][4];
#pragma unroll
    for (int kk = 0; kk < 3; kk++)
        ldsm4(aq[kk], &qs[(wm + l16) * QSTRH + kk * 16 + lh]);

    float m_lo = -1e30f, m_hi = -1e30f, l_lo = 0.f, l_hi = 0.f;
    float o_acc[6][4];
#pragma unroll
    for (int i = 0; i < 6; i++)
#pragma unroll
        for (int r = 0; r < 4; r++) o_acc[i][r] = 0.f;

    int s = 0;
    for (int t = 0; t < 7; t++) {
        CPA_WAIT0();
        __syncthreads();
        const __half* kts = kt + s * HC * KSTRH;
        const __half* vts = vt + s * HC * KSTRH;

        // ---- S = Q^T K : warp tile 16 x 112 (Q fragments in registers) ----
        float sv[14][4];
#pragma unroll
        for (int j = 0; j < 14; j++)
#pragma unroll
            for (int r = 0; r < 4; r++) sv[j][r] = 0.f;
#pragma unroll
        for (int kk = 0; kk < 3; kk++) {
#pragma unroll
            for (int j16 = 0; j16 < 7; j16++) {
                unsigned t4[4];
                ldsm4t(t4, &kts[(kk * 16 + l16) * KSTRH + j16 * 16 + lh]);
                mma16(sv[2 * j16],     aq[kk], t4);
                mma16(sv[2 * j16 + 1], aq[kk], t4 + 2);
            }
        }

        // prefetch next K/V tile
        if (t < 6) stage_kv(s ^ 1, (t + 1) * FTN);
        CPA_COMMIT();

        // ---- row max ----
        float mx_lo = -1e30f, mx_hi = -1e30f;
#pragma unroll
        for (int j = 0; j < 14; j++) {
            mx_lo = fmaxf(mx_lo, fmaxf(sv[j][0], sv[j][1]));
            mx_hi = fmaxf(mx_hi, fmaxf(sv[j][2], sv[j][3]));
        }
#pragma unroll
        for (int o = 1; o < 4; o <<= 1) {
            mx_lo = fmaxf(mx_lo, __shfl_xor_sync(0xffffffffu, mx_lo, o));
            mx_hi = fmaxf(mx_hi, __shfl_xor_sync(0xffffffffu, mx_hi, o));
        }
        float mn_lo = fmaxf(m_lo, mx_lo * scale2);   // log2 units
        float mn_hi = fmaxf(m_hi, mx_hi * scale2);
        float al_lo = ex2(m_lo - mn_lo);
        float al_hi = ex2(m_hi - mn_hi);
        m_lo = mn_lo; m_hi = mn_hi;

        // ---- p = 2^(scale2*s - m) -> packed A fragments ----
        unsigned pk[7][4];
        float sm_lo = 0.f, sm_hi = 0.f;
#pragma unroll
        for (int j16 = 0; j16 < 7; j16++) {
#pragma unroll
            for (int h = 0; h < 2; h++) {
                float* svp = sv[2 * j16 + h];
                float p0 = ex2(fmaf(svp[0], scale2, -mn_lo));
                float p1 = ex2(fmaf(svp[1], scale2, -mn_lo));
                float p2 = ex2(fmaf(svp[2], scale2, -mn_hi));
                float p3 = ex2(fmaf(svp[3], scale2, -mn_hi));
                sm_lo += p0 + p1; sm_hi += p2 + p3;
                pk[j16][2 * h]     = packh2(p0, p1);
                pk[j16][2 * h + 1] = packh2(p2, p3);
            }
        }
#pragma unroll
        for (int o = 1; o < 4; o <<= 1) {
            sm_lo += __shfl_xor_sync(0xffffffffu, sm_lo, o);
            sm_hi += __shfl_xor_sync(0xffffffffu, sm_hi, o);
        }
        l_lo = l_lo * al_lo + sm_lo;
        l_hi = l_hi * al_hi + sm_hi;
#pragma unroll
        for (int i = 0; i < 6; i++) {
            o_acc[i][0] *= al_lo; o_acc[i][1] *= al_lo;
            o_acc[i][2] *= al_hi; o_acc[i][3] *= al_hi;
        }

        // ---- PV: registers P x smem V, 16m x 48c ----
#pragma unroll
        for (int j16 = 0; j16 < 7; j16++) {
#pragma unroll
            for (int ci = 0; ci < 6; ci++) {
                unsigned bf[2];
                bf[0] = *reinterpret_cast<const unsigned*>(&vts[(ci * 8 + g) * KSTRH + j16 * 16 + 2 * tig]);
                bf[1] = *reinterpret_cast<const unsigned*>(&vts[(ci * 8 + g) * KSTRH + j16 * 16 + 8 + 2 * tig]);
                mma16(o_acc[ci], pk[j16], bf);
            }
        }
        s ^= 1;
    }

    // ---- epilogue ----
    float il_lo = 1.f / l_lo;
    float il_hi = 1.f / l_hi;
    bool ok_lo = (m0 + row_lo) < HWSZ;
    bool ok_hi = (m0 + row_hi) < HWSZ;
#pragma unroll
    for (int ci = 0; ci < 6; ci++) {
        int cc = ci * 8 + 2 * tig;
        if (ok_lo) {
            op[(size_t)cc * HWSZ + m0 + row_lo]       = __float2half_rn(o_acc[ci][0] * il_lo);
            op[(size_t)(cc + 1) * HWSZ + m0 + row_lo] = __float2half_rn(o_acc[ci][1] * il_lo);
        }
        if (ok_hi) {
            op[(size_t)cc * HWSZ + m0 + row_hi]       = __float2half_rn(o_acc[ci][2] * il_hi);
            op[(size_t)(cc + 1) * HWSZ + m0 + row_hi] = __float2half_rn(o_acc[ci][3] * il_hi);
        }
    }
}

// ---------------------------------------------------------------------------
extern "C" void kernel_launch(void* const* d_in, const int* in_sizes, int n_in,
                              void* d_out, int out_size)
{
    const float* x   = (const float*)d_in[0];
    const float* Wq  = (const float*)d_in[1];
    const float* bq  = (const float*)d_in[2];
    const float* Wk  = (const float*)d_in[3];
    const float* bk  = (const float*)d_in[4];
    const float* Wv  = (const float*)d_in[5];
    const float* bv  = (const float*)d_in[6];
    const float* Wo  = (const float*)d_in[7];
    const float* bo  = (const float*)d_in[8];
    const float* dww = (const float*)d_in[9];
    const float* dwb = (const float*)d_in[10];
    const float* lng = (const float*)d_in[11];
    const float* lnb = (const float*)d_in[12];
    const float* pww = (const float*)d_in[13];
    float* out = (float*)d_out;

    float *pos;
    __half *qh, *xh, *atth, *xsh, *kh, *vh, *wh;
    cudaGetSymbolAddress((void**)&pos,  g_pos);
    cudaGetSymbolAddress((void**)&qh,   g_qh);
    cudaGetSymbolAddress((void**)&xh,   g_xh);
    cudaGetSymbolAddress((void**)&atth, g_atth);
    cudaGetSymbolAddress((void**)&xsh,  g_xsh);
    cudaGetSymbolAddress((void**)&kh,   g_kh);
    cudaGetSymbolAddress((void**)&vh,   g_vh);
    cudaGetSymbolAddress((void**)&wh,   g_wh);

    __half* whq = wh;
    __half* whk = wh + NCH * NCH;
    __half* whv = wh + 2 * NCH * NCH;
    __half* who = wh + 3 * NCH * NCH;

    cudaFuncSetAttribute(attention_h, cudaFuncAttributeMaxDynamicSharedMemorySize, F_SMEM);

    // 0) all fp32->fp16 conversions in one launch
    conv_all<<<(XN4 + 4 * WN4) / 256, 256>>>(x, Wq, Wk, Wv, Wo, xh, wh);

    dim3 gbig((HWSZ + 127) / 128, 3, BATCH);   // 25 x 3 x 8
    dim3 gkv((NKV + 127) / 128, 6, BATCH);     // 7 x 6 x 8 (k + v fused)

    // 1) q = Wq x + bq  (fp16 out)
    gemm_h<true><<<gbig, 256>>>(whq, nullptr, bq, nullptr, xh, qh, nullptr, NCH, HWSZ);
    // 2) offset net -> pos
    offset_net<<<BATCH * NG * HK, 256>>>(qh, dww, dwb, lng, lnb, pww,
                                         pos, out + YSZ, out + YSZ + PSZ);
    // 3) grid sample (2 positions per thread)
    grid_sample_k<<<dim3((GC * NKV2) / 256, BATCH * NG), 256>>>(xh, pos, xsh);
    // 4) k and v in one launch (fp16 out)
    gemm_h<true><<<gkv, 256>>>(whk, whv, bk, bv, xsh, kh, vh, NCH, NKV);
    // 5) flash attention -> atth (fp16)
    attention_h<<<dim3((HWSZ + FTM - 1) / FTM, BATCH * NH), 256, F_SMEM>>>(qh, kh, vh, atth);
    // 6) y = Wo att + bo
    gemm_h<false><<<gbig, 256>>>(who, nullptr, bo, nullptr, atth, out, nullptr, NCH, HWSZ);
}